// round 4
// baseline (speedup 1.0000x reference)
#include <cuda_runtime.h>
#include <cuda_bf16.h>
#include <cstdint>

// Problem constants (fixed by the dataset).
#define TREES 64
#define DNODES 255      // internal nodes per tree (2^8 - 1)
#define KLEAF 256       // leaves per tree
#define MFEAT 512       // features
#define CCLS 8          // classes
#define BATCH 4096

// Blocking
#define TT 16           // trees per block (gridDim.y = TREES/TT = 4)
#define BB 32           // batch rows per block
#define WB 8            // batch rows per warp (4 warps/block)

// Scratch (no cudaMalloc allowed): preprocessed one-hot feature index and 5*b1
// (half-logit bias for the tanh form of the sigmoid).
__device__ int   g_feat[TREES * DNODES];
__device__ float g_tb[TREES * DNODES];

// ---------------------------------------------------------------------------
// Preprocess: extract one-hot feature index from W1 rows, and tbh = 5*b1.
// One warp per (t,d) row of 512 floats.
// ---------------------------------------------------------------------------
__global__ void prep_kernel(const float* __restrict__ W1,
                            const float* __restrict__ b1)
{
    int row = blockIdx.x * (blockDim.x >> 5) + (threadIdx.x >> 5);
    if (row >= TREES * DNODES) return;
    int lane = threadIdx.x & 31;

    const float4* w4 = reinterpret_cast<const float4*>(W1 + (size_t)row * MFEAT);
    int idx = 0;
#pragma unroll
    for (int i = 0; i < 4; i++) {
        float4 v = w4[i * 32 + lane];
        int base = (i * 32 + lane) * 4;
        if (v.x != 0.0f) idx = base + 0;
        if (v.y != 0.0f) idx = base + 1;
        if (v.z != 0.0f) idx = base + 2;
        if (v.w != 0.0f) idx = base + 3;
    }
#pragma unroll
    for (int off = 16; off; off >>= 1)
        idx = max(idx, __shfl_xor_sync(0xffffffffu, idx, off));
    if (lane == 0) {
        g_feat[row] = idx;
        g_tb[row]   = 5.0f * b1[row];   // sigmoid(10x+10b) = 0.5 + 0.5*tanh(5x+5b)
    }
}

// th = tanh(z) via single MUFU.TANH.
__device__ __forceinline__ float tanhf_hw(float z)
{
    float r;
    asm("tanh.approx.f32 %0, %1;" : "=f"(r) : "f"(z));
    return r;
}

// Pack two floats into a 64-bit register pair.
__device__ __forceinline__ unsigned long long pk2(float lo, float hi)
{
    unsigned long long r;
    asm("mov.b64 %0, {%1, %2};" : "=l"(r) : "f"(lo), "f"(hi));
    return r;
}
// Packed dual FFMA (Blackwell FFMA2, PTX-only).
__device__ __forceinline__ unsigned long long ffma2(unsigned long long a,
                                                    unsigned long long b,
                                                    unsigned long long c)
{
    unsigned long long d;
    asm("fma.rn.f32x2 %0, %1, %2, %3;" : "=l"(d) : "l"(a), "l"(b), "l"(c));
    return d;
}
__device__ __forceinline__ void upk2(unsigned long long v, float& lo, float& hi)
{
    asm("mov.b64 {%0, %1}, %2;" : "=f"(lo), "=f"(hi) : "l"(v));
}

// ---------------------------------------------------------------------------
// Main kernel. Block: 128 threads = 4 warps; covers BB=32 batch rows x TT=16
// trees. Warp w owns batch rows [8w, 8w+8). Lane owns the leaf subtree
// k in [8*lane, 8*lane+8) -> Cw[t] lives in 32 x f32x2 registers per lane.
// Prefix levels 0..4 (nodes 0..30) exchanged via 5 independent shfls.
// The 8 x-gathers are SOFTWARE-PIPELINED: iteration b issues b+1's loads
// before the expansion/contraction so the LDS latency overlaps compute.
// ---------------------------------------------------------------------------
__global__ __launch_bounds__(128, 3)
void forest_kernel(const float* __restrict__ x,
                   const float* __restrict__ Cw,
                   float* __restrict__ out)
{
    extern __shared__ float smem[];
    float*  xs    = smem;                                       // 32*512 floats (64 KB)
    float4* cwsh4 = reinterpret_cast<float4*>(smem + BB * 512); // 512 float4 (8 KB)
    int*    ftsh  = reinterpret_cast<int*>(smem + BB * 512 + 2048);   // 256 ints
    float*  tbsh  = reinterpret_cast<float*>(ftsh + 256);             // 256 floats

    const int tid   = threadIdx.x;
    const int lane  = tid & 31;
    const int warp  = tid >> 5;
    const int bbase = blockIdx.x * BB;
    const int tbase = blockIdx.y * TT;

    // Stage 32 x-rows (64 KB) cooperatively, coalesced float4.
    {
        const float4* x4  = reinterpret_cast<const float4*>(x + (size_t)bbase * MFEAT);
        float4*       xs4 = reinterpret_cast<float4*>(xs);
#pragma unroll
        for (int i = 0; i < 32; i++)
            xs4[i * 128 + tid] = x4[i * 128 + tid];
    }

    // Tree-independent per-lane prefix constants.
    const int pn = (lane < 31) ? lane : 0;        // node this lane evaluates
    const int n1 = 1  + (lane >> 4);
    const int n2 = 3  + (lane >> 3);
    const int n3 = 7  + (lane >> 2);
    const int n4 = 15 + (lane >> 1);
    const float sg0 = (lane & 16) ? 0.5f : -0.5f; // level-l factor = 0.5 + sg*th
    const float sg1 = (lane & 8)  ? 0.5f : -0.5f;
    const float sg2 = (lane & 4)  ? 0.5f : -0.5f;
    const float sg3 = (lane & 2)  ? 0.5f : -0.5f;
    const float sg4 = (lane & 1)  ? 0.5f : -0.5f;

    unsigned long long acc2[WB][4];
#pragma unroll
    for (int b = 0; b < WB; b++)
#pragma unroll
        for (int q = 0; q < 4; q++) acc2[b][q] = 0ull;

    const float* xw = xs + warp * WB * MFEAT;     // this warp's 8 rows

    for (int tt = 0; tt < TT; tt++) {
        const int t = tbase + tt;
        __syncthreads();   // xs ready / previous iteration's shared reads done

        // Stage per-tree node tables.
        for (int i = tid; i < DNODES; i += 128) {
            ftsh[i] = g_feat[t * DNODES + i];
            tbsh[i] = g_tb[t * DNODES + i];
        }
        // Stage Cw[t] (2048 floats) XOR-swizzled so per-lane LDS.128 is
        // bank-conflict-free.
        {
            const float4* cw4 = reinterpret_cast<const float4*>(Cw + (size_t)t * KLEAF * CCLS);
            for (int q = tid; q < 512; q += 128)
                cwsh4[q ^ ((q >> 4) & 7)] = cw4[q];
        }
        __syncthreads();

        // Per-lane packed Cw copy for its 8 leaves (32 x f32x2 = 64 regs).
        unsigned long long cwr2[8][4];
#pragma unroll
        for (int j = 0; j < 8; j++) {
            int k = lane * 8 + j;
#pragma unroll
            for (int h = 0; h < 2; h++) {
                int p4 = (k * 2 + h) ^ (lane & 7);
                float4 v = cwsh4[p4];
                cwr2[j][2 * h + 0] = pk2(v.x, v.y);
                cwr2[j][2 * h + 1] = pk2(v.z, v.w);
            }
        }

        // Per-lane node parameters.
        const int   fpre = ftsh[pn];             const float tpre = tbsh[pn];
        const int   f5   = ftsh[31 + lane];      const float t5   = tbsh[31 + lane];
        const int   f6a  = ftsh[63 + 2 * lane];  const float t6a  = tbsh[63 + 2 * lane];
        const int   f6b  = ftsh[64 + 2 * lane];  const float t6b  = tbsh[64 + 2 * lane];
        const int   f70  = ftsh[127 + 4 * lane]; const float t70  = tbsh[127 + 4 * lane];
        const int   f71  = ftsh[128 + 4 * lane]; const float t71  = tbsh[128 + 4 * lane];
        const int   f72  = ftsh[129 + 4 * lane]; const float t72  = tbsh[129 + 4 * lane];
        const int   f73  = ftsh[130 + 4 * lane]; const float t73  = tbsh[130 + 4 * lane];

        // Prologue: gather x values for b=0.
        float xvp  = xw[fpre];
        float xv5  = xw[f5];
        float xv6a = xw[f6a];
        float xv6b = xw[f6b];
        float xv70 = xw[f70];
        float xv71 = xw[f71];
        float xv72 = xw[f72];
        float xv73 = xw[f73];

#pragma unroll 1
        for (int b = 0; b < WB; b++) {
            // tanh on CURRENT values; thp first so the 5 shfls can issue early.
            float thp  = tanhf_hw(fmaf(5.0f, xvp,  tpre));
            float u0 = __shfl_sync(0xffffffffu, thp, 0);
            float u1 = __shfl_sync(0xffffffffu, thp, n1);
            float u2 = __shfl_sync(0xffffffffu, thp, n2);
            float u3 = __shfl_sync(0xffffffffu, thp, n3);
            float u4 = __shfl_sync(0xffffffffu, thp, n4);

            float th5  = tanhf_hw(fmaf(5.0f, xv5,  t5));
            float th6a = tanhf_hw(fmaf(5.0f, xv6a, t6a));
            float th6b = tanhf_hw(fmaf(5.0f, xv6b, t6b));
            float th70 = tanhf_hw(fmaf(5.0f, xv70, t70));
            float th71 = tanhf_hw(fmaf(5.0f, xv71, t71));
            float th72 = tanhf_hw(fmaf(5.0f, xv72, t72));
            float th73 = tanhf_hw(fmaf(5.0f, xv73, t73));

            // PREFETCH next iteration's gathers (latency hidden under the
            // expansion + contraction below). Clamped wrap keeps it branch-free.
            const float* xrn = xw + ((b + 1) & (WB - 1)) * MFEAT;
            xvp  = xrn[fpre];
            xv5  = xrn[f5];
            xv6a = xrn[f6a];
            xv6b = xrn[f6b];
            xv70 = xrn[f70];
            xv71 = xrn[f71];
            xv72 = xrn[f72];
            xv73 = xrn[f73];

            // Prefix product over levels 0..4.
            float g0 = fmaf(sg0, u0, 0.5f);
            float g1 = fmaf(sg1, u1, 0.5f);
            float g2 = fmaf(sg2, u2, 0.5f);
            float g3 = fmaf(sg3, u3, 0.5f);
            float g4 = fmaf(sg4, u4, 0.5f);
            float p = (g0 * g1) * (g2 * g3) * g4;

            // Subtree expansion (levels 5..7) -> 8 leaf probabilities.
            float f5n = fmaf(-0.5f, th5, 0.5f),  f5p = fmaf(0.5f, th5, 0.5f);
            float pA = p * f5n, pB = p * f5p;
            float a6n = fmaf(-0.5f, th6a, 0.5f), a6p = fmaf(0.5f, th6a, 0.5f);
            float b6n = fmaf(-0.5f, th6b, 0.5f), b6p = fmaf(0.5f, th6b, 0.5f);
            float p00 = pA * a6n, p01 = pA * a6p;
            float p10 = pB * b6n, p11 = pB * b6p;
            float c0n = fmaf(-0.5f, th70, 0.5f), c0p = fmaf(0.5f, th70, 0.5f);
            float c1n = fmaf(-0.5f, th71, 0.5f), c1p = fmaf(0.5f, th71, 0.5f);
            float c2n = fmaf(-0.5f, th72, 0.5f), c2p = fmaf(0.5f, th72, 0.5f);
            float c3n = fmaf(-0.5f, th73, 0.5f), c3p = fmaf(0.5f, th73, 0.5f);
            float P[8];
            P[0] = p00 * c0n;  P[1] = p00 * c0p;
            P[2] = p01 * c1n;  P[3] = p01 * c1p;
            P[4] = p10 * c2n;  P[5] = p10 * c2p;
            P[6] = p11 * c3n;  P[7] = p11 * c3p;

            // Contraction with register-resident Cw: 32 FFMA2 (4 indep chains).
#pragma unroll
            for (int j = 0; j < 8; j++) {
                unsigned long long pp = pk2(P[j], P[j]);
#pragma unroll
                for (int q = 0; q < 4; q++)
                    acc2[b][q] = ffma2(pp, cwr2[j][q], acc2[b][q]);
            }
        }
    }

    // Unpack, cross-lane reduce (leaves were split over lanes), write out.
    const float inv_t = 1.0f / (float)TREES;
#pragma unroll
    for (int b = 0; b < WB; b++) {
        float acc[CCLS];
#pragma unroll
        for (int q = 0; q < 4; q++)
            upk2(acc2[b][q], acc[2 * q], acc[2 * q + 1]);
#pragma unroll
        for (int c = 0; c < CCLS; c++) {
            float v = acc[c];
#pragma unroll
            for (int off = 16; off; off >>= 1)
                v += __shfl_xor_sync(0xffffffffu, v, off);
            acc[c] = v;
        }
        if (lane < CCLS) {
            int brow = bbase + warp * WB + b;
            atomicAdd(&out[brow * CCLS + lane], acc[lane] * inv_t);
        }
    }
}

// ---------------------------------------------------------------------------
extern "C" void kernel_launch(void* const* d_in, const int* in_sizes, int n_in,
                              void* d_out, int out_size)
{
    // Identify inputs by element count (order per metadata: input, W1, b1,
    // Bpos, Bneg, Cw — Bpos/Bneg are structurally fixed and unused).
    const float* x  = nullptr;
    const float* W1 = nullptr;
    const float* b1 = nullptr;
    const float* Cw = nullptr;
    for (int i = 0; i < n_in; i++) {
        switch (in_sizes[i]) {
            case BATCH * MFEAT:          x  = (const float*)d_in[i]; break; // 2097152
            case TREES * DNODES * MFEAT: W1 = (const float*)d_in[i]; break; // 8355840
            case TREES * DNODES:         b1 = (const float*)d_in[i]; break; // 16320
            case TREES * KLEAF * CCLS:   Cw = (const float*)d_in[i]; break; // 131072
            default: break;                                                 // Bpos/Bneg
        }
    }
    float* out = (float*)d_out;

    static const size_t smem_bytes =
        (size_t)(BB * 512 + 2048 + 256 + 256) * 4;
    cudaFuncSetAttribute(forest_kernel,
                         cudaFuncAttributeMaxDynamicSharedMemorySize,
                         (int)smem_bytes);

    cudaMemsetAsync(d_out, 0, (size_t)out_size * sizeof(float), 0);

    {
        int rows = TREES * DNODES;
        int warps_per_block = 8;
        int blocks = (rows + warps_per_block - 1) / warps_per_block;
        prep_kernel<<<blocks, warps_per_block * 32>>>(W1, b1);
    }

    dim3 grid(BATCH / BB, TREES / TT);
    forest_kernel<<<grid, 128, smem_bytes>>>(x, Cw, out);
}